// round 1
// baseline (speedup 1.0000x reference)
#include <cuda_runtime.h>
#include <cstddef>

// Problem constants (fixed by the reference):
//   T = 512 (block size), E = 64 (n_embed), H = 128 (ffn hidden = out)
//   out[b, i, j, c] = (gelu(pos_table[tril(i-j)] @ W1 + b1) @ W2 + b2)[c]
// Key insight: only 512 distinct rows exist (indexed by dist = max(i-j, 0)),
// and the batch dim is a broadcast. Compute a 512x128 table, then scatter.

#define T_DIM 512
#define E_DIM 64
#define H_DIM 128

// Scratch table: 512 rows x 128 floats = 256 KB (static device memory; no allocation).
__device__ float g_table[T_DIM * H_DIM];

// ---------------------------------------------------------------------------
// Kernel A: build the table.
// One block per distance d (512 blocks), 128 threads = one output column each.
//   h[j]   = gelu_exact(sum_k pos_table[d,k] * W1[k,j] + b1[j])
//   out[j] = sum_k h[k] * W2[k,j] + b2[j]
// ---------------------------------------------------------------------------
__global__ void build_table_kernel(const float* __restrict__ pos_table,
                                   const float* __restrict__ W1,
                                   const float* __restrict__ b1,
                                   const float* __restrict__ W2,
                                   const float* __restrict__ b2) {
    __shared__ float sp[E_DIM];
    __shared__ float sh[H_DIM];

    const int d = blockIdx.x;      // distance row 0..511
    const int j = threadIdx.x;     // output column 0..127

    if (j < E_DIM) sp[j] = pos_table[d * E_DIM + j];
    __syncthreads();

    // First GEMM row: [1,64] @ [64,128]
    float acc = b1[j];
#pragma unroll
    for (int k = 0; k < E_DIM; k++) {
        acc = fmaf(sp[k], W1[k * H_DIM + j], acc);
    }
    // Exact GELU (approximate=False): 0.5*x*(1+erf(x/sqrt(2)))
    float g = 0.5f * acc * (1.0f + erff(acc * 0.70710678118654752f));
    sh[j] = g;
    __syncthreads();

    // Second GEMM row: [1,128] @ [128,128]
    float acc2 = b2[j];
#pragma unroll
    for (int k = 0; k < H_DIM; k++) {
        acc2 = fmaf(sh[k], W2[k * H_DIM + j], acc2);
    }
    g_table[d * H_DIM + j] = acc2;
}

// ---------------------------------------------------------------------------
// Kernel B: scatter along diagonals.
// blockIdx.x = k in 0..1022  ->  d = k - 511 in [-511, 511] = i - j
// All entries on one diagonal share table row max(d, 0): load the 512-byte
// row ONCE into registers (float4 per lane), then stream stores. This keeps
// L2 read traffic ~0 and leaves pure HBM store bandwidth as the limiter.
// blockIdx.y = batch. 128 threads: 4 warps each handle every 4th entry,
// each lane stores one float4 (32 lanes x 16B = full 512B row, coalesced).
// ---------------------------------------------------------------------------
__global__ void __launch_bounds__(128, 8)
scatter_kernel(float4* __restrict__ out) {
    const int k = blockIdx.x;          // 0..1022
    const int d = k - (T_DIM - 1);     // i - j
    const int b = blockIdx.y;
    const int lane = threadIdx.x & 31;
    const int sub  = threadIdx.x >> 5; // 0..3

    const int row = d > 0 ? d : 0;     // tril clamps upper triangle to 0
    const float4 v = reinterpret_cast<const float4*>(g_table)[row * (H_DIM / 4) + lane];

    const int i0 = d > 0 ? d : 0;
    const int i1 = d > 0 ? (T_DIM - 1) : (T_DIM - 1 + d);

    for (int i = i0 + sub; i <= i1; i += 4) {
        const int j = i - d;
        const size_t off =
            (((size_t)b * T_DIM + i) * T_DIM + j) * (H_DIM / 4) + lane;
        out[off] = v;
    }
}

extern "C" void kernel_launch(void* const* d_in, const int* in_sizes, int n_in,
                              void* d_out, int out_size) {
    // Reference inputs in order: b, pos_table, W1, b1, W2, b2.
    // Be robust to whether the python scalar 'b' is materialized as input 0.
    int base = 0;
    if (n_in >= 6) {
        base = 1;                       // d_in[0] is the scalar b
    } else if (n_in == 5 && in_sizes[0] == T_DIM * E_DIM) {
        base = 0;                       // b not passed
    }
    const float* pos_table = (const float*)d_in[base + 0];
    const float* W1        = (const float*)d_in[base + 1];
    const float* b1        = (const float*)d_in[base + 2];
    const float* W2        = (const float*)d_in[base + 3];
    const float* b2        = (const float*)d_in[base + 4];

    // Derive batch from output size (avoids a device->host copy of scalar b).
    const int bsz = out_size / (T_DIM * T_DIM * H_DIM);

    build_table_kernel<<<T_DIM, H_DIM>>>(pos_table, W1, b1, W2, b2);

    dim3 grid(2 * T_DIM - 1, bsz);      // 1023 diagonals x batch
    scatter_kernel<<<grid, 128>>>((float4*)d_out);
}